// round 17
// baseline (speedup 1.0000x reference)
#include <cuda_runtime.h>
#include <cuda_fp16.h>
#include <cstdint>
#include <cstddef>

// B=128, S=2048, I=256, H=512, O=256
// SINGLE-KERNEL persistent fp16 LSTM. R17: re-partitioned to
//  128 CTAs = 8 batch-bands(16 rows) x 16 column-CTAs(32 h-cols x 4 gates).
//  -> 16-CTA band barriers (drain ~437 cyc vs 875), half staging, half L2.
// Core (R14-proven): weights-in-registers (Breg 192 b32/thread), ldmatrix A,
// mma.sync m16n8k16, 128-wide K chunks (6/step), 3-slot cp.async ring depth-2,
// smem Cs/cst epilogue with rcp.approx, atomic-chain band barrier.

#define TB 256
#define NCTA 128
#define ASTR 68                   // b32 per A row (136 halves); row stride 272B
#define ASLOT_B (16 * ASTR * 4)   // 4352 B per ring slot (16 rows)
#define OFF_BS 0                  // 128 floats bias
#define OFF_CST 512               // 512 floats cell state
#define OFF_CS 2560               // 16*132 floats gate preacts (8448B)
#define OFF_A 11008               // ring: 3 slots; also weight-staging scratch
#define SMEM_BYTES (OFF_A + 128 * ASTR * 4) // 11008 + 34816 = 45824

static __device__ __half g_x16[128 * 2048 * 256];
static __device__ __half g_h16[2][128 * 512];
static __device__ int g_cnt[8];
static __device__ volatile int g_flag[8];
static __device__ int g_arr;
static __device__ volatile int g_gen;

__device__ __forceinline__ void cp16(unsigned dst, const void* src) {
    asm volatile("cp.async.cg.shared.global [%0], [%1], 16;\n" ::"r"(dst), "l"(src));
}
__device__ __forceinline__ void cp_commit() { asm volatile("cp.async.commit_group;\n"); }
__device__ __forceinline__ void cp_wait1() { asm volatile("cp.async.wait_group 1;\n"); }

__device__ __forceinline__ void mma_f16(float c[4], unsigned a0, unsigned a1, unsigned a2,
                                        unsigned a3, unsigned b0, unsigned b1) {
    asm volatile(
        "mma.sync.aligned.m16n8k16.row.col.f32.f16.f16.f32 "
        "{%0,%1,%2,%3},{%4,%5,%6,%7},{%8,%9},{%0,%1,%2,%3};"
        : "+f"(c[0]), "+f"(c[1]), "+f"(c[2]), "+f"(c[3])
        : "r"(a0), "r"(a1), "r"(a2), "r"(a3), "r"(b0), "r"(b1));
}
__device__ __forceinline__ void sth(__half* p, __half v) {
    unsigned short u = __half_as_ushort(v);
    asm volatile("st.global.cg.u16 [%0], %1;" ::"l"(p), "h"(u));
}
__device__ __forceinline__ float frcp(float x) {
    float r;
    asm("rcp.approx.f32 %0, %1;" : "=f"(r) : "f"(x));
    return r;
}
__device__ __forceinline__ float fsig(float x) { return frcp(1.f + __expf(-x)); }
__device__ __forceinline__ float ftanh(float x) {
    float a = fabsf(x);
    float e = __expf(2.f * a);
    float r = 1.f - 2.f * frcp(1.f + e);
    return copysignf(r, x);
}

__global__ void __launch_bounds__(TB, 1)
lstm_all(const float* __restrict__ x,
         const float* __restrict__ W_ix, const float* __restrict__ W_fx,
         const float* __restrict__ W_ox, const float* __restrict__ W_gx,
         const float* __restrict__ W_ih, const float* __restrict__ b_ih,
         const float* __restrict__ W_fh, const float* __restrict__ b_fh,
         const float* __restrict__ W_oh, const float* __restrict__ b_oh,
         const float* __restrict__ W_gh, const float* __restrict__ b_gh,
         const float* __restrict__ W_ph, const float* __restrict__ b_ph,
         float* __restrict__ out) {
    extern __shared__ __align__(16) char smem[];
    float* bs = (float*)(smem + OFF_BS);
    float* cst = (float*)(smem + OFF_CST);
    float* Cs = (float*)(smem + OFF_CS);
    const unsigned sb = (unsigned)__cvta_generic_to_shared(smem);

    const int tid = threadIdx.x;
    const int cta = blockIdx.x;
    const int band = cta >> 4;   // 0..7 (16 batch rows each)
    const int col = cta & 15;    // 0..15 (32 h-cols each)
    const int hc0 = col * 32;
    const int brow0 = band * 16;

    const int lane = tid & 31;
    const int w = tid >> 5;      // warp cols = w*16 .. w*16+15
    const int g = lane >> 2;
    const int tq = lane & 3;
    const int wc0 = w * 16;

    // ================= PHASE 0: x -> fp16, zero h(0) =================
    {
        const size_t n2 = (size_t)128 * 2048 * 256 / 2;
        for (size_t i = (size_t)cta * TB + tid; i < n2; i += (size_t)NCTA * TB) {
            float2 v = ((const float2*)x)[i];
            ((__half2*)g_x16)[i] = __floats2half2_rn(v.x, v.y);
        }
        for (int j = cta * TB + tid; j < 128 * 512 / 2; j += NCTA * TB)
            ((__half2*)g_h16[0])[j] = __floats2half2_rn(0.f, 0.f);
    }

    const float* Whp[4] = {W_ih, W_fh, W_oh, W_gh};
    const float* Wxp[4] = {W_ix, W_fx, W_ox, W_gx};
    const float* bbp[4] = {b_ih, b_fh, b_oh, b_gh};

    // n ordering: n = gate*32 + hcl  (gate = n>>5, hcl = n&31)
    for (int i = tid; i < 128; i += TB) bs[i] = bbp[i >> 5][hc0 + (i & 31)];
    for (int i = tid; i < 512; i += TB) cst[i] = 0.f;

    // ---- Hoist B fragments to registers, one 128-K chunk at a time,
    // staged through scratch at OFF_A (128 n x 136 halves = 34816 B).
    unsigned Breg[6][8][2][2];
    {
        __half* Wt = (__half*)(smem + OFF_A);
        const unsigned* Wu = (const unsigned*)(smem + OFF_A);
#pragma unroll
        for (int kc = 0; kc < 6; ++kc) {
            __syncthreads();
            for (int idx = tid; idx < 128 * 128; idx += TB) {
                int n = idx >> 7;
                int kl = idx & 127;
                int k = kc * 128 + kl;
                int gate = n >> 5;
                int hc = hc0 + (n & 31);
                float v = (k < 256) ? Wxp[gate][hc * 256 + k]
                                    : Whp[gate][hc * 512 + (k - 256)];
                Wt[n * 136 + kl] = __float2half_rn(v);
            }
            __syncthreads();
#pragma unroll
            for (int kk = 0; kk < 8; ++kk)
#pragma unroll
                for (int nt = 0; nt < 2; ++nt) {
                    int wn = (wc0 + nt * 8 + g) * ASTR + kk * 8 + tq;
                    Breg[kc][kk][nt][0] = Wu[wn];
                    Breg[kc][kk][nt][1] = Wu[wn + 4];
                }
        }
        __syncthreads();
    }

    // ================= ENTRY BARRIER (generation counter, replay-safe) ====
    if (tid == 0) {
        int G = g_gen;
        asm volatile("fence.acq_rel.gpu;" ::: "memory");
        int old = atomicAdd(&g_arr, 1);
        if (old == NCTA - 1) {
            for (int b = 0; b < 8; ++b) g_flag[b] = 0;
            atomicExch(&g_arr, 0);
            asm volatile("fence.acq_rel.gpu;" ::: "memory");
            g_gen = G + 1;
        } else {
            while (g_gen == G) { __nanosleep(64); }
            asm volatile("fence.acq_rel.gpu;" ::: "memory");
        }
    }
    __syncthreads();

    // ================= MAINLOOP =================
    // A staging: 1 cp16/thread/chunk (16 rows x 16 units of 16B)
    const int ar = tid >> 4; // 0..15 row
    const int aq = tid & 15; // 0..15
    const unsigned dA0 = (unsigned)ar * 272 + (unsigned)aq * 16;
    const size_t xrow = ((size_t)(brow0 + ar) * 2048) * 256;
    const size_t hrow = (size_t)(brow0 + ar) * 512;

    // ldmatrix: rows 0..15 (all warps), two 16B k-halves
    const unsigned a_off = (unsigned)((lane & 15) * 272 + ((lane >> 4) & 1) * 16);

    auto issue_x = [&](int sti, int ci, int slot) {
        if (sti >= 2048) return;
        unsigned d = sb + OFF_A + (unsigned)slot * ASLOT_B + dA0;
        cp16(d, g_x16 + xrow + (size_t)sti * 256 + ci * 128 + aq * 8);
    };
    auto issue_h = [&](int sti, int ci, int slot) {
        unsigned d = sb + OFF_A + (unsigned)slot * ASLOT_B + dA0;
        cp16(d, g_h16[sti & 1] + hrow + (ci - 2) * 128 + aq * 8);
    };

    issue_x(0, 0, 0); cp_commit();
    issue_x(0, 1, 1); cp_commit();

    for (int ti = 0; ti < 2048; ++ti) {
        float acc[2][4];
#pragma unroll
        for (int n = 0; n < 2; n++)
#pragma unroll
            for (int j = 0; j < 4; j++) acc[n][j] = 0.f;

#pragma unroll
        for (int kc = 0; kc < 6; ++kc) {
            cp_wait1();
            __syncthreads();
            if (kc < 4) issue_h(ti, kc + 2, (kc + 2) % 3);
            else        issue_x(ti + 1, kc - 4, (kc + 2) % 3);
            cp_commit();

            const unsigned abase = sb + OFF_A + (unsigned)((kc % 3) * ASLOT_B) + a_off;
#pragma unroll
            for (int kk = 0; kk < 8; ++kk) {
                unsigned a0, a1, a2, a3;
                asm volatile(
                    "ldmatrix.sync.aligned.m8n8.x4.shared.b16 {%0,%1,%2,%3}, [%4];"
                    : "=r"(a0), "=r"(a1), "=r"(a2), "=r"(a3)
                    : "r"(abase + (unsigned)(kk * 32)));
                mma_f16(acc[0], a0, a1, a2, a3, Breg[kc][kk][0][0], Breg[kc][kk][0][1]);
                mma_f16(acc[1], a0, a1, a2, a3, Breg[kc][kk][1][0], Breg[kc][kk][1][1]);
            }
        }

        // ---- Gate preactivations to Cs (16 rows x 128 cols, stride 132)
#pragma unroll
        for (int nt = 0; nt < 2; ++nt) {
            int c0 = wc0 + nt * 8 + 2 * tq;
            Cs[g * 132 + c0] = acc[nt][0];
            Cs[g * 132 + c0 + 1] = acc[nt][1];
            Cs[(g + 8) * 132 + c0] = acc[nt][2];
            Cs[(g + 8) * 132 + c0 + 1] = acc[nt][3];
        }
        __syncthreads();

        // ---- Cell update (fp32, rcp.approx), h store (fp16, st.cg -> L2)
        __half* hcur = g_h16[(ti + 1) & 1];
        for (int it = tid; it < 512; it += TB) {
            int r = it >> 5, hc = it & 31;
            const float* Crow = Cs + r * 132;
            float zi = Crow[hc] + bs[hc];
            float zf = Crow[32 + hc] + bs[32 + hc];
            float zo = Crow[64 + hc] + bs[64 + hc];
            float zg = Crow[96 + hc] + bs[96 + hc];
            float gi_ = fsig(zi);
            float gf = fsig(zf);
            float go = fsig(zo);
            float gg = ftanh(zg);
            float c = gg * gi_ + cst[it] * gf;
            cst[it] = c;
            float h = ftanh(c) * go;
            sth(&hcur[(size_t)(brow0 + r) * 512 + hc0 + hc], __float2half_rn(h));
        }
        __syncthreads();

        // ---- Band barrier: proven atomic chain + nanosleep, now 16 CTAs
        if (tid == 0) {
            asm volatile("fence.acq_rel.gpu;" ::: "memory");
            int prev = atomicAdd(&g_cnt[band], 1);
            if (prev == 15) {
                atomicExch(&g_cnt[band], 0);
                g_flag[band] = ti + 1;
            } else {
                while (g_flag[band] < ti + 1) { __nanosleep(64); }
                asm volatile("fence.acq_rel.gpu;" ::: "memory");
            }
        }
        __syncthreads();
    }

    // ================= TAIL: projection for row band*16+col =================
    asm volatile("cp.async.wait_group 0;\n" ::: "memory");
    __syncthreads();
    {
        float* hsp = (float*)(smem + OFF_A);
        const int row = band * 16 + col; // covered by own band's final barrier
        const __half* hr = g_h16[0] + (size_t)row * 512; // h(2048), 2048 even
        for (int i = tid; i < 512; i += TB) hsp[i] = __half2float(hr[i]);
        __syncthreads();
        int o = tid;
        const float* wr = W_ph + o * 512;
        float acc = b_ph[o];
#pragma unroll 8
        for (int k = 0; k < 512; ++k) acc += hsp[k] * wr[k];
        out[row * 256 + o] = acc;
    }
}

extern "C" void kernel_launch(void* const* d_in, const int* in_sizes, int n_in,
                              void* d_out, int out_size) {
    (void)in_sizes; (void)n_in; (void)out_size;
    const float* x    = (const float*)d_in[0];
    const float* W_ix = (const float*)d_in[1];
    const float* W_fx = (const float*)d_in[2];
    const float* W_ox = (const float*)d_in[3];
    const float* W_gx = (const float*)d_in[4];
    const float* W_ih = (const float*)d_in[5];
    const float* b_ih = (const float*)d_in[6];
    const float* W_fh = (const float*)d_in[7];
    const float* b_fh = (const float*)d_in[8];
    const float* W_oh = (const float*)d_in[9];
    const float* b_oh = (const float*)d_in[10];
    const float* W_gh = (const float*)d_in[11];
    const float* b_gh = (const float*)d_in[12];
    const float* W_ph = (const float*)d_in[13];
    const float* b_ph = (const float*)d_in[14];

    cudaFuncSetAttribute(lstm_all, cudaFuncAttributeMaxDynamicSharedMemorySize, SMEM_BYTES);
    lstm_all<<<NCTA, TB, SMEM_BYTES>>>(x, W_ix, W_fx, W_ox, W_gx,
                                       W_ih, b_ih, W_fh, b_fh, W_oh, b_oh, W_gh, b_gh,
                                       W_ph, b_ph, (float*)d_out);
}